// round 13
// baseline (speedup 1.0000x reference)
#include <cuda_runtime.h>
#include <cuda_fp16.h>
#include <cstdint>

// ---------------------------------------------------------------------------
// FMoELinearProj via legacy HMMA (mma.sync.m16n8k16.f16), single fp16 digit.
// R12: fixes R11's GEMM2 k-tile coverage bug — 128 threads must load 2 x 16B
// chunks per operand tile (64 rows x 64B), not 1. GEMM1 unchanged (best
// config); GEMM2 CTA 64x64, 128 thr, occ 4 for wave balance (1024 CTAs).
// ---------------------------------------------------------------------------

#define BM 128
#define BN 128
#define NTH 256
#define SROW 80                       // padded smem row (64B data + 16B pad)
#define TILEB (128 * SROW)            // 10240 B per fp16 tile (128 rows)
#define OFF_BHI TILEB
#define STAGEB (2 * TILEB)            // Ahi, Bhi
#define BIAS_OFF (2 * STAGEB)         // 40960
#define SMEM_TOTAL (BIAS_OFF + 512)

// GEMM2 geometry
#define BM2 64
#define BN2 64
#define NTH2 128
#define TILEB2 (64 * SROW)            // 5120 B
#define OFF_BHI2 TILEB2
#define STAGEB2 (2 * TILEB2)          // 10240
#define SMEM_TOTAL2 (2 * STAGEB2)     // 20480

__device__ int  g_off[65];
__device__ int2 g_tiles[1024];        // BM=128 granularity (GEMM1)
__device__ int  g_ntiles;
__device__ int2 g_tiles2[2048];       // BM2=64 granularity (GEMM2)
__device__ int  g_ntiles2;
__device__ __half g_yh[8192ull * 4096];

// ------------------------------- helpers -----------------------------------
__device__ __forceinline__ uint32_t smem_u32(const void* p) {
    uint32_t a;
    asm("{ .reg .u64 t; cvta.to.shared.u64 t, %1; cvt.u32.u64 %0, t; }"
        : "=r"(a) : "l"(p));
    return a;
}
__device__ __forceinline__ void ldsm4(uint32_t* r, uint32_t addr) {
    asm volatile("ldmatrix.sync.aligned.m8n8.x4.shared.b16 {%0,%1,%2,%3}, [%4];"
                 : "=r"(r[0]), "=r"(r[1]), "=r"(r[2]), "=r"(r[3]) : "r"(addr));
}
__device__ __forceinline__ void mma16816(float* c, const uint32_t* a,
                                         const uint32_t* b) {
    asm volatile(
        "mma.sync.aligned.m16n8k16.row.col.f32.f16.f16.f32 "
        "{%0,%1,%2,%3}, {%4,%5,%6,%7}, {%8,%9}, {%0,%1,%2,%3};"
        : "+f"(c[0]), "+f"(c[1]), "+f"(c[2]), "+f"(c[3])
        : "r"(a[0]), "r"(a[1]), "r"(a[2]), "r"(a[3]), "r"(b[0]), "r"(b[1]));
}
__device__ __forceinline__ void cpa16(uint32_t dst, const void* src,
                                      uint32_t ssize) {
    asm volatile("cp.async.cg.shared.global [%0], [%1], 16, %2;"
                 :: "r"(dst), "l"(src), "r"(ssize) : "memory");
}
#define CP_COMMIT() asm volatile("cp.async.commit_group;" ::: "memory")
#define CP_WAIT0()  asm volatile("cp.async.wait_group 0;" ::: "memory")

__device__ __forceinline__ void sts128(uint32_t a, uint32_t r0, uint32_t r1,
                                       uint32_t r2, uint32_t r3) {
    asm volatile("st.shared.v4.b32 [%0], {%1, %2, %3, %4};"
                 :: "r"(a), "r"(r0), "r"(r1), "r"(r2), "r"(r3) : "memory");
}
// pack two fp32 -> fp16x2 (round-to-nearest)
__device__ __forceinline__ uint32_t h2rn(float e0, float e1) {
    uint32_t d;
    asm("cvt.rn.f16x2.f32 %0, %1, %2;" : "=r"(d) : "f"(e1), "f"(e0));
    return d;
}
// Round 8 fp32 to fp16 digits; store 16B.
__device__ __forceinline__ void round_sts(uint32_t dst, float4 u0, float4 u1) {
    sts128(dst, h2rn(u0.x, u0.y), h2rn(u0.z, u0.w),
                h2rn(u1.x, u1.y), h2rn(u1.z, u1.w));
}

// ------------------------------ setup kernel -------------------------------
__global__ void setup_kernel(const int* __restrict__ counts, int E) {
    if (threadIdx.x == 0 && blockIdx.x == 0) {
        int off = 0, nt = 0, nt2 = 0;
        for (int e = 0; e < E; ++e) {
            g_off[e] = off;
            int c = counts[e];
            for (int m = 0; m < c; m += BM)  { g_tiles[nt].x = e;  g_tiles[nt].y = m;  ++nt; }
            for (int m = 0; m < c; m += BM2) { g_tiles2[nt2].x = e; g_tiles2[nt2].y = m; ++nt2; }
            off += c;
        }
        g_off[E] = off;
        g_ntiles = nt;
        g_ntiles2 = nt2;
    }
}

// ------------------------------ GEMM1 kernel -------------------------------
// y[row, n] = sum_k x[row, k] * W[e, n, k] + bias, emitted as fp16 to g_yh.
__global__ __launch_bounds__(NTH, 2)
void moe_g1(const float* __restrict__ Af, const float* __restrict__ Bf,
            const float* __restrict__ bias, int K, int N)
{
    const int tile = blockIdx.y;
    if (tile >= g_ntiles) return;
    const int e    = g_tiles[tile].x;
    const int m0   = g_tiles[tile].y;
    const int row0 = g_off[e] + m0;
    int mrows = g_off[e + 1] - g_off[e] - m0;
    if (mrows > BM) mrows = BM;
    const int n0 = blockIdx.x * BN;

    extern __shared__ char smem[];
    const uint32_t sb = smem_u32(smem);
    const int tid = threadIdx.x, wid = tid >> 5, lane = tid & 31;
    const int warp_m = wid & 3, warp_n = wid >> 2;   // 4 x 2 warps of 32x64

    if (tid < 32)
        ((float4*)(smem + BIAS_OFF))[tid] =
            *(const float4*)&bias[(size_t)e * N + n0 + tid * 4];

    const int r0c = tid >> 2;
    const int ccol = (tid & 3) * 8;
    const uint32_t sdst0 = (uint32_t)(r0c * SROW) + (tid & 3) * 16;
    const uint32_t sdst1 = sdst0 + 64 * SROW;
    const bool aok0 = r0c < mrows;
    const bool aok1 = (r0c + 64) < mrows;
    const float4 z4 = make_float4(0.f, 0.f, 0.f, 0.f);

    const float* Afp0 = Af + (size_t)(row0 + r0c) * K + ccol;
    const float* Afp1 = Af + (size_t)(row0 + r0c + 64) * K + ccol;
    const float* Bfp0 = Bf + ((size_t)e * N + n0 + r0c) * K + ccol;
    const float* Bfp1 = Bf + ((size_t)e * N + n0 + r0c + 64) * K + ccol;

    float4 a00, a01, a10, a11, b00, b01, b10, b11;

    a00 = aok0 ? *(const float4*)Afp0 : z4;
    a01 = aok0 ? *(const float4*)(Afp0 + 4) : z4;
    a10 = aok1 ? *(const float4*)Afp1 : z4;
    a11 = aok1 ? *(const float4*)(Afp1 + 4) : z4;
    b00 = *(const float4*)Bfp0;
    b01 = *(const float4*)(Bfp0 + 4);
    b10 = *(const float4*)Bfp1;
    b11 = *(const float4*)(Bfp1 + 4);
    round_sts(sb + sdst0, a00, a01);
    round_sts(sb + sdst1, a10, a11);
    round_sts(sb + OFF_BHI + sdst0, b00, b01);
    round_sts(sb + OFF_BHI + sdst1, b10, b11);
    __syncthreads();

    float acc[2][8][4];
#pragma unroll
    for (int mi = 0; mi < 2; ++mi)
#pragma unroll
        for (int nj = 0; nj < 8; ++nj)
#pragma unroll
            for (int q = 0; q < 4; ++q) acc[mi][nj][q] = 0.f;

    const uint32_t a_off = (uint32_t)(warp_m * 32 + (lane & 15)) * SROW +
                           ((lane >> 4) * 16);
    const uint32_t b_off = (uint32_t)(warp_n * 64 + (lane & 7) +
                                      ((lane >> 4) & 1) * 8) * SROW +
                           (((lane >> 3) & 1) * 16);

    const int nk = K >> 5;
    for (int kt = 0; kt < nk; ++kt) {
        const uint32_t stg  = sb + (uint32_t)(kt & 1) * STAGEB;
        const uint32_t nstg = sb + (uint32_t)((kt + 1) & 1) * STAGEB;
        const bool more = (kt + 1 < nk);
        if (more) {
            const int ko = (kt + 1) * 32;
            a00 = aok0 ? *(const float4*)(Afp0 + ko) : z4;
            a01 = aok0 ? *(const float4*)(Afp0 + ko + 4) : z4;
            a10 = aok1 ? *(const float4*)(Afp1 + ko) : z4;
            a11 = aok1 ? *(const float4*)(Afp1 + ko + 4) : z4;
            b00 = *(const float4*)(Bfp0 + ko);
            b01 = *(const float4*)(Bfp0 + ko + 4);
            b10 = *(const float4*)(Bfp1 + ko);
            b11 = *(const float4*)(Bfp1 + ko + 4);
        }
#pragma unroll
        for (int k16 = 0; k16 < 2; ++k16) {
            const uint32_t kb = k16 * 32;
            uint32_t ah[2][4], bh[4][4];
            ldsm4(ah[0], stg + a_off + kb);
            ldsm4(ah[1], stg + a_off + kb + 16 * SROW);
#pragma unroll
            for (int bj = 0; bj < 4; ++bj)
                ldsm4(bh[bj], stg + OFF_BHI + b_off + kb + bj * 16 * SROW);
#pragma unroll
            for (int mi = 0; mi < 2; ++mi)
#pragma unroll
                for (int nj = 0; nj < 8; ++nj)
                    mma16816(acc[mi][nj], ah[mi], &bh[nj >> 1][(nj & 1) * 2]);
        }
        if (more) {
            round_sts(nstg + sdst0, a00, a01);
            round_sts(nstg + sdst1, a10, a11);
            round_sts(nstg + OFF_BHI + sdst0, b00, b01);
            round_sts(nstg + OFF_BHI + sdst1, b10, b11);
        }
        __syncthreads();
    }

    // epilogue: y as fp16
    const float* bs = (const float*)(smem + BIAS_OFF);
    uint32_t* yh32 = (uint32_t*)g_yh;
#pragma unroll
    for (int mi = 0; mi < 2; ++mi) {
        const int r = warp_m * 32 + mi * 16 + (lane >> 2);
#pragma unroll
        for (int nj = 0; nj < 8; ++nj) {
            const int c = warp_n * 64 + nj * 8 + (lane & 3) * 2;
            float2 v0 = make_float2(acc[mi][nj][0], acc[mi][nj][1]);
            float2 v1 = make_float2(acc[mi][nj][2], acc[mi][nj][3]);
            const float b0 = bs[c], b1 = bs[c + 1];
            v0.x += b0; v0.y += b1;
            v1.x += b0; v1.y += b1;
            if (r < mrows) {
                const size_t ix = ((size_t)(row0 + r) * N + n0 + c) >> 1;
                yh32[ix] = h2rn(v0.x, v0.y);
            }
            if (r + 8 < mrows) {
                const size_t ix = ((size_t)(row0 + r + 8) * N + n0 + c) >> 1;
                yh32[ix] = h2rn(v1.x, v1.y);
            }
        }
    }
}

// ------------------------------ GEMM2 kernel -------------------------------
// out[row, n] = sum_k y[row, k] * comp[e, n, k]. CTA 64x64, 128 thr, occ 4.
// Each thread loads TWO 16B chunks per operand tile (full 64B k-row coverage).
__global__ __launch_bounds__(NTH2, 4)
void moe_g2(const __half* __restrict__ Ah, const float* __restrict__ Bf,
            float* __restrict__ Cf, int K, int N)
{
    const int tile = blockIdx.y;
    if (tile >= g_ntiles2) return;
    const int e    = g_tiles2[tile].x;
    const int m0   = g_tiles2[tile].y;
    const int row0 = g_off[e] + m0;
    int mrows = g_off[e + 1] - g_off[e] - m0;
    if (mrows > BM2) mrows = BM2;
    const int n0 = blockIdx.x * BN2;

    extern __shared__ char smem[];
    const uint32_t sb = smem_u32(smem);
    const int tid = threadIdx.x, wid = tid >> 5, lane = tid & 31;
    const int warp_m = wid & 1, warp_n = wid >> 1;   // 2 x 2 warps of 32x32

    // load mapping: chunk ids tid and tid+128; row = id>>2, col = (id&3)*16B.
    const int rA0 = tid >> 2;               // 0..31
    const int rA1 = (tid + 128) >> 2;       // 32..63
    const int cc0 = (tid & 3) * 8;          // fp32/fp16 element offset
    const uint32_t sd0 = (uint32_t)(rA0 * SROW) + (tid & 3) * 16;
    const uint32_t sd1 = (uint32_t)(rA1 * SROW) + (tid & 3) * 16;
    const bool aok0 = rA0 < mrows;
    const bool aok1 = rA1 < mrows;
    const uint32_t szA0 = aok0 ? 16u : 0u;
    const uint32_t szA1 = aok1 ? 16u : 0u;

    const char*  Ahp0 = (const char*)(Ah + (size_t)(row0 + rA0) * K + cc0);
    const char*  Ahp1 = (const char*)(Ah + (size_t)(row0 + rA1) * K + cc0);
    const float* Bfp0 = Bf + ((size_t)e * N + n0 + rA0) * K + cc0;
    const float* Bfp1 = Bf + ((size_t)e * N + n0 + rA1) * K + cc0;

    float4 b00, b01, b10, b11;

    // prologue: stage kt=0
    cpa16(sb + sd0, Ahp0, szA0);
    cpa16(sb + sd1, Ahp1, szA1);
    CP_COMMIT();
    b00 = *(const float4*)Bfp0;
    b01 = *(const float4*)(Bfp0 + 4);
    b10 = *(const float4*)Bfp1;
    b11 = *(const float4*)(Bfp1 + 4);
    round_sts(sb + OFF_BHI2 + sd0, b00, b01);
    round_sts(sb + OFF_BHI2 + sd1, b10, b11);
    CP_WAIT0();
    __syncthreads();

    float acc[2][4][4];
#pragma unroll
    for (int mi = 0; mi < 2; ++mi)
#pragma unroll
        for (int nj = 0; nj < 4; ++nj)
#pragma unroll
            for (int q = 0; q < 4; ++q) acc[mi][nj][q] = 0.f;

    const uint32_t a_off = (uint32_t)(warp_m * 32 + (lane & 15)) * SROW +
                           ((lane >> 4) * 16);
    const uint32_t b_off = (uint32_t)(warp_n * 32 + (lane & 7) +
                                      ((lane >> 4) & 1) * 8) * SROW +
                           (((lane >> 3) & 1) * 16);

    const int nk = K >> 5;
    for (int kt = 0; kt < nk; ++kt) {
        const uint32_t stg  = sb + (uint32_t)(kt & 1) * STAGEB2;
        const uint32_t nstg = sb + (uint32_t)((kt + 1) & 1) * STAGEB2;
        const bool more = (kt + 1 < nk);
        if (more) {
            const int ko = (kt + 1) * 32;
            cpa16(nstg + sd0, Ahp0 + ko * 2, szA0);
            cpa16(nstg + sd1, Ahp1 + ko * 2, szA1);
            CP_COMMIT();
            b00 = *(const float4*)(Bfp0 + ko);
            b01 = *(const float4*)(Bfp0 + ko + 4);
            b10 = *(const float4*)(Bfp1 + ko);
            b11 = *(const float4*)(Bfp1 + ko + 4);
        }
#pragma unroll
        for (int k16 = 0; k16 < 2; ++k16) {
            const uint32_t kb = k16 * 32;
            uint32_t ah[2][4], bh[2][4];
            ldsm4(ah[0], stg + a_off + kb);
            ldsm4(ah[1], stg + a_off + kb + 16 * SROW);
            ldsm4(bh[0], stg + OFF_BHI2 + b_off + kb);
            ldsm4(bh[1], stg + OFF_BHI2 + b_off + kb + 16 * SROW);
#pragma unroll
            for (int mi = 0; mi < 2; ++mi)
#pragma unroll
                for (int nj = 0; nj < 4; ++nj)
                    mma16816(acc[mi][nj], ah[mi], &bh[nj >> 1][(nj & 1) * 2]);
        }
        if (more) {
            round_sts(nstg + OFF_BHI2 + sd0, b00, b01);
            round_sts(nstg + OFF_BHI2 + sd1, b10, b11);
            CP_WAIT0();
        }
        __syncthreads();
    }

    // epilogue: fp32 out
#pragma unroll
    for (int mi = 0; mi < 2; ++mi) {
        const int r = warp_m * 32 + mi * 16 + (lane >> 2);
#pragma unroll
        for (int nj = 0; nj < 4; ++nj) {
            const int c = warp_n * 32 + nj * 8 + (lane & 3) * 2;
            float2 v0 = make_float2(acc[mi][nj][0], acc[mi][nj][1]);
            float2 v1 = make_float2(acc[mi][nj][2], acc[mi][nj][3]);
            if (r < mrows)
                *(float2*)&Cf[(size_t)(row0 + r) * N + n0 + c] = v0;
            if (r + 8 < mrows)
                *(float2*)&Cf[(size_t)(row0 + r + 8) * N + n0 + c] = v1;
        }
    }
}

// ------------------------------- launch -------------------------------------
extern "C" void kernel_launch(void* const* d_in, const int* in_sizes, int n_in,
                              void* d_out, int out_size) {
    const float* inp  = (const float*)d_in[0];
    const int*   cnt  = (const int*)  d_in[1];
    const float* wgt  = (const float*)d_in[2];
    const float* bias = (const float*)d_in[3];
    const float* comp = (const float*)d_in[4];
    float* out = (float*)d_out;

    const int E     = in_sizes[1];
    const int D_out = in_sizes[3] / E;
    const int D_in  = in_sizes[2] / in_sizes[3];
    const int T     = in_sizes[0] / D_in;
    const int S     = in_sizes[4] / in_sizes[3];
    const int maxtiles  = T / BM + E;
    const int maxtiles2 = T / BM2 + E;

    cudaFuncSetAttribute(moe_g1,
                         cudaFuncAttributeMaxDynamicSharedMemorySize, SMEM_TOTAL);
    cudaFuncSetAttribute(moe_g2,
                         cudaFuncAttributeMaxDynamicSharedMemorySize, SMEM_TOTAL2);

    __half* yh;
    cudaGetSymbolAddress((void**)&yh, g_yh);

    setup_kernel<<<1, 1>>>(cnt, E);

    // GEMM1: y = x @ W^T + b  (fp16 rounding in-loop; y emitted fp16)
    moe_g1<<<dim3(D_out / BN, maxtiles), NTH, SMEM_TOTAL>>>(
        inp, wgt, bias, D_in, D_out);
    // GEMM2: out = y @ C^T  (y fp16 via cp.async; comp rounded in-loop)
    moe_g2<<<dim3(S / BN2, maxtiles2), NTH2, SMEM_TOTAL2>>>(
        yh, comp, out, D_out, S);
}

// round 14
// speedup vs baseline: 1.1136x; 1.1136x over previous
#include <cuda_runtime.h>
#include <cuda_fp16.h>
#include <cstdint>

// ---------------------------------------------------------------------------
// FMoELinearProj via legacy HMMA (mma.sync.m16n8k16.f16), single fp16 digit.
// R13: revert to R10 (best: 432 us) — CTA 128x128, 256 thr, 8 warps of 32x64,
// occ 2, 2-stage smem — and remove the serial setup kernel: each CTA resolves
// (expert, m0) from counts with a <=16-iter scan hidden under the prologue.
// GEMM1 emits y as fp16; GEMM2 pulls it via cp.async.
// ---------------------------------------------------------------------------

#define BM 128
#define BN 128
#define NTH 256
#define SROW 80                       // padded smem row (64B data + 16B pad)
#define TILEB (128 * SROW)            // 10240 B per fp16 tile
#define OFF_BHI TILEB
#define STAGEB (2 * TILEB)            // Ahi, Bhi
#define BIAS_OFF (2 * STAGEB)         // 40960
#define SMEM_TOTAL (BIAS_OFF + 512)

__device__ __half g_yh[8192ull * 4096];

// ------------------------------- helpers -----------------------------------
__device__ __forceinline__ uint32_t smem_u32(const void* p) {
    uint32_t a;
    asm("{ .reg .u64 t; cvta.to.shared.u64 t, %1; cvt.u32.u64 %0, t; }"
        : "=r"(a) : "l"(p));
    return a;
}
__device__ __forceinline__ void ldsm4(uint32_t* r, uint32_t addr) {
    asm volatile("ldmatrix.sync.aligned.m8n8.x4.shared.b16 {%0,%1,%2,%3}, [%4];"
                 : "=r"(r[0]), "=r"(r[1]), "=r"(r[2]), "=r"(r[3]) : "r"(addr));
}
__device__ __forceinline__ void mma16816(float* c, const uint32_t* a,
                                         const uint32_t* b) {
    asm volatile(
        "mma.sync.aligned.m16n8k16.row.col.f32.f16.f16.f32 "
        "{%0,%1,%2,%3}, {%4,%5,%6,%7}, {%8,%9}, {%0,%1,%2,%3};"
        : "+f"(c[0]), "+f"(c[1]), "+f"(c[2]), "+f"(c[3])
        : "r"(a[0]), "r"(a[1]), "r"(a[2]), "r"(a[3]), "r"(b[0]), "r"(b[1]));
}
__device__ __forceinline__ void cpa16(uint32_t dst, const void* src,
                                      uint32_t ssize) {
    asm volatile("cp.async.cg.shared.global [%0], [%1], 16, %2;"
                 :: "r"(dst), "l"(src), "r"(ssize) : "memory");
}
#define CP_COMMIT() asm volatile("cp.async.commit_group;" ::: "memory")
#define CP_WAIT0()  asm volatile("cp.async.wait_group 0;" ::: "memory")

__device__ __forceinline__ void sts128(uint32_t a, uint32_t r0, uint32_t r1,
                                       uint32_t r2, uint32_t r3) {
    asm volatile("st.shared.v4.b32 [%0], {%1, %2, %3, %4};"
                 :: "r"(a), "r"(r0), "r"(r1), "r"(r2), "r"(r3) : "memory");
}
// pack two fp32 -> fp16x2 (round-to-nearest)
__device__ __forceinline__ uint32_t h2rn(float e0, float e1) {
    uint32_t d;
    asm("cvt.rn.f16x2.f32 %0, %1, %2;" : "=r"(d) : "f"(e1), "f"(e0));
    return d;
}
// Round 8 fp32 to fp16 digits; store 16B.
__device__ __forceinline__ void round_sts(uint32_t dst, float4 u0, float4 u1) {
    sts128(dst, h2rn(u0.x, u0.y), h2rn(u0.z, u0.w),
                h2rn(u1.x, u1.y), h2rn(u1.z, u1.w));
}

// ------------------------------ main GEMM kernel ---------------------------
// C[row, n] = sum_k A[row, k] * B[e, n, k] (+ bias).
// A_F16: A pre-rounded (g_yh), fetched via cp.async; else fp32 rounded in-loop.
// F16_OUT: write C as fp16 into g_yh; else fp32 to Cf.
// Tile resolution: per-CTA scan over counts (<=E iterations, L1-resident).
template <bool ADD_BIAS, bool A_F16, bool F16_OUT>
__global__ __launch_bounds__(NTH, 2)
void moe_hmma(const float* __restrict__ Af,
              const __half* __restrict__ Ah,
              const float* __restrict__ Bf,
              const float* __restrict__ bias, float* __restrict__ Cf,
              const int* __restrict__ counts, int E,
              int K, int N)
{
    // ---- resolve (e, m0, row0, mrows) from blockIdx.y by scanning counts ---
    int ty = blockIdx.y;
    int off = 0, e = 0, cexp = 0, m0 = 0;
    bool valid = false;
    for (e = 0; e < E; ++e) {
        cexp = counts[e];
        const int nt = (cexp + BM - 1) / BM;
        if (ty < nt) { m0 = ty * BM; valid = true; break; }
        ty -= nt;
        off += cexp;
    }
    if (!valid) return;
    const int row0 = off + m0;
    int mrows = cexp - m0;
    if (mrows > BM) mrows = BM;
    const int n0 = blockIdx.x * BN;

    extern __shared__ char smem[];
    const uint32_t sb = smem_u32(smem);
    const int tid = threadIdx.x, wid = tid >> 5, lane = tid & 31;
    const int warp_m = wid & 3, warp_n = wid >> 2;   // 4 x 2 warps of 32x64

    if (ADD_BIAS && tid < 32)
        ((float4*)(smem + BIAS_OFF))[tid] =
            *(const float4*)&bias[(size_t)e * N + n0 + tid * 4];

    // ---- load mapping: 2 chunks (8 fp32 / 16B fp16) per thread per tile ----
    const int r0c = tid >> 2;              // rows r0c and r0c+64
    const int ccol = (tid & 3) * 8;        // fp32 column offset in k-tile
    const uint32_t sdst0 = (uint32_t)(r0c * SROW) + (tid & 3) * 16;
    const uint32_t sdst1 = sdst0 + 64 * SROW;
    const bool aok0 = r0c < mrows;
    const bool aok1 = (r0c + 64) < mrows;
    const float4 z4 = make_float4(0.f, 0.f, 0.f, 0.f);

    const float* Afp0 = Af + (size_t)(row0 + r0c) * K + ccol;
    const float* Afp1 = Af + (size_t)(row0 + r0c + 64) * K + ccol;
    const char*  Ahp0 = (const char*)(Ah + (size_t)(row0 + r0c) * K + ccol);
    const char*  Ahp1 = (const char*)(Ah + (size_t)(row0 + r0c + 64) * K + ccol);
    const float* Bfp0 = Bf + ((size_t)e * N + n0 + r0c) * K + ccol;
    const float* Bfp1 = Bf + ((size_t)e * N + n0 + r0c + 64) * K + ccol;
    const uint32_t sz0 = aok0 ? 16u : 0u, sz1 = aok1 ? 16u : 0u;

    float4 a00, a01, a10, a11, b00, b01, b10, b11;

    // -------- prologue: stage kt=0 into buffer 0 --------
    if (A_F16) {
        cpa16(sb + sdst0, Ahp0, sz0);
        cpa16(sb + sdst1, Ahp1, sz1);
        CP_COMMIT();
    } else {
        a00 = aok0 ? *(const float4*)Afp0 : z4;
        a01 = aok0 ? *(const float4*)(Afp0 + 4) : z4;
        a10 = aok1 ? *(const float4*)Afp1 : z4;
        a11 = aok1 ? *(const float4*)(Afp1 + 4) : z4;
    }
    b00 = *(const float4*)Bfp0;
    b01 = *(const float4*)(Bfp0 + 4);
    b10 = *(const float4*)Bfp1;
    b11 = *(const float4*)(Bfp1 + 4);
    if (!A_F16) {
        round_sts(sb + sdst0, a00, a01);
        round_sts(sb + sdst1, a10, a11);
    }
    round_sts(sb + OFF_BHI + sdst0, b00, b01);
    round_sts(sb + OFF_BHI + sdst1, b10, b11);
    if (A_F16) CP_WAIT0();
    __syncthreads();

    float acc[2][8][4];
#pragma unroll
    for (int mi = 0; mi < 2; ++mi)
#pragma unroll
        for (int nj = 0; nj < 8; ++nj)
#pragma unroll
            for (int q = 0; q < 4; ++q) acc[mi][nj][q] = 0.f;

    const uint32_t a_off = (uint32_t)(warp_m * 32 + (lane & 15)) * SROW +
                           ((lane >> 4) * 16);
    const uint32_t b_off = (uint32_t)(warp_n * 64 + (lane & 7) +
                                      ((lane >> 4) & 1) * 8) * SROW +
                           (((lane >> 3) & 1) * 16);

    const int nk = K >> 5;
    for (int kt = 0; kt < nk; ++kt) {
        const uint32_t stg  = sb + (uint32_t)(kt & 1) * STAGEB;
        const uint32_t nstg = sb + (uint32_t)((kt + 1) & 1) * STAGEB;
        const bool more = (kt + 1 < nk);
        if (more) {
            const int ko = (kt + 1) * 32;
            if (A_F16) {
                cpa16(nstg + sdst0, Ahp0 + ko * 2, sz0);
                cpa16(nstg + sdst1, Ahp1 + ko * 2, sz1);
                CP_COMMIT();
            } else {
                a00 = aok0 ? *(const float4*)(Afp0 + ko) : z4;
                a01 = aok0 ? *(const float4*)(Afp0 + ko + 4) : z4;
                a10 = aok1 ? *(const float4*)(Afp1 + ko) : z4;
                a11 = aok1 ? *(const float4*)(Afp1 + ko + 4) : z4;
            }
            b00 = *(const float4*)(Bfp0 + ko);
            b01 = *(const float4*)(Bfp0 + ko + 4);
            b10 = *(const float4*)(Bfp1 + ko);
            b11 = *(const float4*)(Bfp1 + ko + 4);
        }
#pragma unroll
        for (int k16 = 0; k16 < 2; ++k16) {
            const uint32_t kb = k16 * 32;
            uint32_t ah[2][4], bh[4][4];
            ldsm4(ah[0], stg + a_off + kb);
            ldsm4(ah[1], stg + a_off + kb + 16 * SROW);
#pragma unroll
            for (int bj = 0; bj < 4; ++bj)
                ldsm4(bh[bj], stg + OFF_BHI + b_off + kb + bj * 16 * SROW);
#pragma unroll
            for (int mi = 0; mi < 2; ++mi)
#pragma unroll
                for (int nj = 0; nj < 8; ++nj)
                    mma16816(acc[mi][nj], ah[mi], &bh[nj >> 1][(nj & 1) * 2]);
        }
        if (more) {
            if (!A_F16) {
                round_sts(nstg + sdst0, a00, a01);
                round_sts(nstg + sdst1, a10, a11);
            }
            round_sts(nstg + OFF_BHI + sdst0, b00, b01);
            round_sts(nstg + OFF_BHI + sdst1, b10, b11);
            if (A_F16) CP_WAIT0();
        }
        __syncthreads();
    }

    // ------------------------------ epilogue --------------------------------
    const float* bs = (const float*)(smem + BIAS_OFF);
    uint32_t* yh32 = (uint32_t*)g_yh;
#pragma unroll
    for (int mi = 0; mi < 2; ++mi) {
        const int r = warp_m * 32 + mi * 16 + (lane >> 2);
#pragma unroll
        for (int nj = 0; nj < 8; ++nj) {
            const int c = warp_n * 64 + nj * 8 + (lane & 3) * 2;
            float2 v0 = make_float2(acc[mi][nj][0], acc[mi][nj][1]);
            float2 v1 = make_float2(acc[mi][nj][2], acc[mi][nj][3]);
            if (ADD_BIAS) {
                const float b0 = bs[c], b1 = bs[c + 1];
                v0.x += b0; v0.y += b1;
                v1.x += b0; v1.y += b1;
            }
            if (F16_OUT) {
                if (r < mrows) {
                    const size_t ix = ((size_t)(row0 + r) * N + n0 + c) >> 1;
                    yh32[ix] = h2rn(v0.x, v0.y);
                }
                if (r + 8 < mrows) {
                    const size_t ix = ((size_t)(row0 + r + 8) * N + n0 + c) >> 1;
                    yh32[ix] = h2rn(v1.x, v1.y);
                }
            } else {
                if (r < mrows)
                    *(float2*)&Cf[(size_t)(row0 + r) * N + n0 + c] = v0;
                if (r + 8 < mrows)
                    *(float2*)&Cf[(size_t)(row0 + r + 8) * N + n0 + c] = v1;
            }
        }
    }
}

// ------------------------------- launch -------------------------------------
extern "C" void kernel_launch(void* const* d_in, const int* in_sizes, int n_in,
                              void* d_out, int out_size) {
    const float* inp  = (const float*)d_in[0];
    const int*   cnt  = (const int*)  d_in[1];
    const float* wgt  = (const float*)d_in[2];
    const float* bias = (const float*)d_in[3];
    const float* comp = (const float*)d_in[4];
    float* out = (float*)d_out;

    const int E     = in_sizes[1];
    const int D_out = in_sizes[3] / E;
    const int D_in  = in_sizes[2] / in_sizes[3];
    const int T     = in_sizes[0] / D_in;
    const int S     = in_sizes[4] / in_sizes[3];
    const int maxtiles = T / BM + E;   // upper bound on sum_e ceil(count_e/BM)

    cudaFuncSetAttribute(moe_hmma<true, false, true>,
                         cudaFuncAttributeMaxDynamicSharedMemorySize, SMEM_TOTAL);
    cudaFuncSetAttribute(moe_hmma<false, true, false>,
                         cudaFuncAttributeMaxDynamicSharedMemorySize, SMEM_TOTAL);

    __half* yh;
    cudaGetSymbolAddress((void**)&yh, g_yh);

    // GEMM1: y = x @ W^T + b  (x/W rounded in-loop; y emitted fp16)
    moe_hmma<true, false, true><<<dim3(D_out / BN, maxtiles), NTH, SMEM_TOTAL>>>(
        inp, nullptr, wgt, bias, nullptr, cnt, E, D_in, D_out);
    // GEMM2: out = y @ C^T  (y fp16 via cp.async; comp rounded in-loop)
    moe_hmma<false, true, false><<<dim3(S / BN, maxtiles), NTH, SMEM_TOTAL>>>(
        nullptr, yh, comp, nullptr, out, cnt, E, D_out, S);
}

// round 15
// speedup vs baseline: 1.2252x; 1.1002x over previous
#include <cuda_runtime.h>
#include <cuda_fp16.h>
#include <cstdint>

// ---------------------------------------------------------------------------
// FMoELinearProj via legacy HMMA (mma.sync.m16n8k16.f16), single fp16 digit.
// R14: L1-traffic fix — R8's geometry (CTA 128x256, 8 warps of 64x64:
// ~61KB/kt L1 vs 102KB for 32x64) with R10's 1-MMA-per-tile scheme.
// A always fp16 via cp.async (x pre-rounded by tiny prepass; y fp16 from
// GEMM1). B (W / comp) rounded in-loop. 2-stage smem, occ 1, setup kernel.
// ---------------------------------------------------------------------------

#define BM 128
#define BN 256
#define NTH 256
#define SROW 80                        // padded smem row: 64B data + 16B pad
#define ATILE (128 * SROW)             // 10240
#define BTILE (256 * SROW)             // 20480
#define OFF_B ATILE
#define STAGEB (ATILE + BTILE)         // 30720
#define BIAS_OFF (2 * STAGEB)          // 61440
#define SMEM_TOTAL (BIAS_OFF + 1024 + 128)

__device__ int  g_off[65];
__device__ int2 g_tiles[1024];
__device__ int  g_ntiles;
__device__ __half g_xh[8192ull * 1024];
__device__ __half g_yh[8192ull * 4096];

// ------------------------------- helpers -----------------------------------
__device__ __forceinline__ uint32_t smem_u32(const void* p) {
    uint32_t a;
    asm("{ .reg .u64 t; cvta.to.shared.u64 t, %1; cvt.u32.u64 %0, t; }"
        : "=r"(a) : "l"(p));
    return a;
}
__device__ __forceinline__ void ldsm4(uint32_t* r, uint32_t addr) {
    asm volatile("ldmatrix.sync.aligned.m8n8.x4.shared.b16 {%0,%1,%2,%3}, [%4];"
                 : "=r"(r[0]), "=r"(r[1]), "=r"(r[2]), "=r"(r[3]) : "r"(addr));
}
__device__ __forceinline__ void mma16816(float* c, const uint32_t* a,
                                         const uint32_t* b) {
    asm volatile(
        "mma.sync.aligned.m16n8k16.row.col.f32.f16.f16.f32 "
        "{%0,%1,%2,%3}, {%4,%5,%6,%7}, {%8,%9}, {%0,%1,%2,%3};"
        : "+f"(c[0]), "+f"(c[1]), "+f"(c[2]), "+f"(c[3])
        : "r"(a[0]), "r"(a[1]), "r"(a[2]), "r"(a[3]), "r"(b[0]), "r"(b[1]));
}
__device__ __forceinline__ void cpa16(uint32_t dst, const void* src,
                                      uint32_t ssize) {
    asm volatile("cp.async.cg.shared.global [%0], [%1], 16, %2;"
                 :: "r"(dst), "l"(src), "r"(ssize) : "memory");
}
#define CP_COMMIT() asm volatile("cp.async.commit_group;" ::: "memory")
#define CP_WAIT0()  asm volatile("cp.async.wait_group 0;" ::: "memory")

__device__ __forceinline__ void sts128(uint32_t a, uint32_t r0, uint32_t r1,
                                       uint32_t r2, uint32_t r3) {
    asm volatile("st.shared.v4.b32 [%0], {%1, %2, %3, %4};"
                 :: "r"(a), "r"(r0), "r"(r1), "r"(r2), "r"(r3) : "memory");
}
__device__ __forceinline__ uint32_t h2rn(float e0, float e1) {
    uint32_t d;
    asm("cvt.rn.f16x2.f32 %0, %1, %2;" : "=r"(d) : "f"(e1), "f"(e0));
    return d;
}
__device__ __forceinline__ void round_sts(uint32_t dst, float4 u0, float4 u1) {
    sts128(dst, h2rn(u0.x, u0.y), h2rn(u0.z, u0.w),
                h2rn(u1.x, u1.y), h2rn(u1.z, u1.w));
}

// --------------------------- x -> fp16 prepass -----------------------------
__global__ void round_kernel(const float* __restrict__ src,
                             __half* __restrict__ dst, long n) {
    long stride = (long)gridDim.x * blockDim.x * 4;
    for (long i = ((long)blockIdx.x * blockDim.x + threadIdx.x) * 4; i < n;
         i += stride) {
        float4 v = *(const float4*)(src + i);
        uint2 h;
        h.x = h2rn(v.x, v.y);
        h.y = h2rn(v.z, v.w);
        *(uint2*)(dst + i) = h;
    }
}

// ------------------------------ setup kernel -------------------------------
__global__ void setup_kernel(const int* __restrict__ counts, int E) {
    if (threadIdx.x == 0 && blockIdx.x == 0) {
        int off = 0, nt = 0;
        for (int e = 0; e < E; ++e) {
            g_off[e] = off;
            int c = counts[e];
            for (int m = 0; m < c; m += BM) { g_tiles[nt].x = e; g_tiles[nt].y = m; ++nt; }
            off += c;
        }
        g_off[E] = off;
        g_ntiles = nt;
    }
}

// ------------------------------ main GEMM kernel ---------------------------
// C[row, n] = sum_k A[row, k] * B[e, n, k] (+ bias).
// A: fp16 (g_xh or g_yh) via cp.async. B: fp32, rounded in-loop.
// F16_OUT: write C as fp16 into g_yh; else fp32 to Cf.
template <bool ADD_BIAS, bool F16_OUT>
__global__ __launch_bounds__(NTH, 1)
void moe_hmma(const __half* __restrict__ Ah,
              const float* __restrict__ Bf,
              const float* __restrict__ bias, float* __restrict__ Cf,
              int K, int N)
{
    const int tile = blockIdx.y;
    if (tile >= g_ntiles) return;
    const int e    = g_tiles[tile].x;
    const int m0   = g_tiles[tile].y;
    const int row0 = g_off[e] + m0;
    int mrows = g_off[e + 1] - g_off[e] - m0;
    if (mrows > BM) mrows = BM;
    const int n0 = blockIdx.x * BN;

    extern __shared__ char smem[];
    const uint32_t sb = smem_u32(smem);
    const int tid = threadIdx.x, wid = tid >> 5, lane = tid & 31;
    const int warp_m = wid & 1, warp_n = wid >> 1;   // 2 x 4 warps of 64x64

    if (ADD_BIAS && tid < 64)
        ((float4*)(smem + BIAS_OFF))[tid] =
            *(const float4*)&bias[(size_t)e * N + n0 + tid * 4];

    // ---- A: 2 cp.async chunks per thread (128 rows x 4 chunks) ----
    const int rA0 = tid >> 2;                 // 0..63
    const int rA1 = (tid + 256) >> 2;         // 64..127
    const uint32_t cby = (uint32_t)(tid & 3) * 16;
    const uint32_t sdA0 = (uint32_t)(rA0 * SROW) + cby;
    const uint32_t sdA1 = (uint32_t)(rA1 * SROW) + cby;
    const uint32_t szA0 = (rA0 < mrows) ? 16u : 0u;
    const uint32_t szA1 = (rA1 < mrows) ? 16u : 0u;
    const int ccol = (tid & 3) * 8;           // element offset in k-tile
    const char* Ahp0 = (const char*)(Ah + (size_t)(row0 + rA0) * K + ccol);
    const char* Ahp1 = (const char*)(Ah + (size_t)(row0 + rA1) * K + ccol);

    // ---- B: 4 row chunks per thread (256 rows x 4 chunks) ----
    const int rB = tid >> 2;                  // base row, +64 per q
    const uint32_t sdB = (uint32_t)(rB * SROW) + cby;
    const float* Bbase = Bf + ((size_t)e * N + n0 + rB) * K + ccol;
    const size_t Bstep = (size_t)64 * K;

    // -------- prologue: stage kt=0 into buffer 0 --------
    cpa16(sb + sdA0, Ahp0, szA0);
    cpa16(sb + sdA1, Ahp1, szA1);
    CP_COMMIT();
#pragma unroll
    for (int q = 0; q < 4; ++q) {
        const float* bp = Bbase + (size_t)q * Bstep;
        float4 u0 = *(const float4*)bp;
        float4 u1 = *(const float4*)(bp + 4);
        round_sts(sb + OFF_B + sdB + (uint32_t)q * (64 * SROW), u0, u1);
    }
    CP_WAIT0();
    __syncthreads();

    float acc[4][8][4];
#pragma unroll
    for (int mi = 0; mi < 4; ++mi)
#pragma unroll
        for (int nj = 0; nj < 8; ++nj)
#pragma unroll
            for (int q = 0; q < 4; ++q) acc[mi][nj][q] = 0.f;

    const uint32_t a_off = (uint32_t)(warp_m * 64 + (lane & 15)) * SROW +
                           ((lane >> 4) * 16);
    const uint32_t b_off = (uint32_t)(warp_n * 64 + (lane & 7) +
                                      ((lane >> 4) & 1) * 8) * SROW +
                           (((lane >> 3) & 1) * 16);

    const int nk = K >> 5;
    for (int kt = 0; kt < nk; ++kt) {
        const uint32_t stg  = sb + (uint32_t)(kt & 1) * STAGEB;
        const uint32_t nstg = sb + (uint32_t)((kt + 1) & 1) * STAGEB;
        const bool more = (kt + 1 < nk);
        const int ko = (kt + 1) * 32;

        float4 b0[4], b1[4];
        if (more) {
            cpa16(nstg + sdA0, Ahp0 + ko * 2, szA0);
            cpa16(nstg + sdA1, Ahp1 + ko * 2, szA1);
            CP_COMMIT();
#pragma unroll
            for (int q = 0; q < 4; ++q) {
                const float* bp = Bbase + (size_t)q * Bstep + ko;
                b0[q] = *(const float4*)bp;
                b1[q] = *(const float4*)(bp + 4);
            }
        }

        // ------------------------- MMA phase (2 x k16) ----------------------
#pragma unroll
        for (int k16 = 0; k16 < 2; ++k16) {
            const uint32_t kb = k16 * 32;
            uint32_t ah[4][4], bh[4][4];
#pragma unroll
            for (int mi = 0; mi < 4; ++mi)
                ldsm4(ah[mi], stg + a_off + kb + mi * 16 * SROW);
#pragma unroll
            for (int bj = 0; bj < 4; ++bj)
                ldsm4(bh[bj], stg + OFF_B + b_off + kb + bj * 16 * SROW);
#pragma unroll
            for (int mi = 0; mi < 4; ++mi)
#pragma unroll
                for (int nj = 0; nj < 8; ++nj)
                    mma16816(acc[mi][nj], ah[mi], &bh[nj >> 1][(nj & 1) * 2]);
        }

        if (more) {
#pragma unroll
            for (int q = 0; q < 4; ++q)
                round_sts(nstg + OFF_B + sdB + (uint32_t)q * (64 * SROW),
                          b0[q], b1[q]);
            CP_WAIT0();
        }
        __syncthreads();
    }

    // ------------------------------ epilogue --------------------------------
    const float* bs = (const float*)(smem + BIAS_OFF);
    uint32_t* yh32 = (uint32_t*)g_yh;
#pragma unroll
    for (int mi = 0; mi < 4; ++mi) {
        const int r = warp_m * 64 + mi * 16 + (lane >> 2);
#pragma unroll
        for (int nj = 0; nj < 8; ++nj) {
            const int c = warp_n * 64 + nj * 8 + (lane & 3) * 2;
            float2 v0 = make_float2(acc[mi][nj][0], acc[mi][nj][1]);
            float2 v1 = make_float2(acc[mi][nj][2], acc[mi][nj][3]);
            if (ADD_BIAS) {
                const float b0 = bs[c], b1 = bs[c + 1];
                v0.x += b0; v0.y += b1;
                v1.x += b0; v1.y += b1;
            }
            if (F16_OUT) {
                if (r < mrows) {
                    const size_t ix = ((size_t)(row0 + r) * N + n0 + c) >> 1;
                    yh32[ix] = h2rn(v0.x, v0.y);
                }
                if (r + 8 < mrows) {
                    const size_t ix = ((size_t)(row0 + r + 8) * N + n0 + c) >> 1;
                    yh32[ix] = h2rn(v1.x, v1.y);
                }
            } else {
                if (r < mrows)
                    *(float2*)&Cf[(size_t)(row0 + r) * N + n0 + c] = v0;
                if (r + 8 < mrows)
                    *(float2*)&Cf[(size_t)(row0 + r + 8) * N + n0 + c] = v1;
            }
        }
    }
}

// ------------------------------- launch -------------------------------------
extern "C" void kernel_launch(void* const* d_in, const int* in_sizes, int n_in,
                              void* d_out, int out_size) {
    const float* inp  = (const float*)d_in[0];
    const int*   cnt  = (const int*)  d_in[1];
    const float* wgt  = (const float*)d_in[2];
    const float* bias = (const float*)d_in[3];
    const float* comp = (const float*)d_in[4];
    float* out = (float*)d_out;

    const int E     = in_sizes[1];
    const int D_out = in_sizes[3] / E;
    const int D_in  = in_sizes[2] / in_sizes[3];
    const int T     = in_sizes[0] / D_in;
    const int S     = in_sizes[4] / in_sizes[3];
    const int maxtiles = T / BM + E;

    cudaFuncSetAttribute(moe_hmma<true, true>,
                         cudaFuncAttributeMaxDynamicSharedMemorySize, SMEM_TOTAL);
    cudaFuncSetAttribute(moe_hmma<false, false>,
                         cudaFuncAttributeMaxDynamicSharedMemorySize, SMEM_TOTAL);

    __half *xh, *yh;
    cudaGetSymbolAddress((void**)&xh, g_xh);
    cudaGetSymbolAddress((void**)&yh, g_yh);

    setup_kernel<<<1, 1>>>(cnt, E);
    round_kernel<<<296, 256>>>(inp, xh, (long)in_sizes[0]);

    // GEMM1: y = x @ W^T + b  (x fp16 via cp.async; W rounded in-loop; y fp16)
    moe_hmma<true, true><<<dim3(D_out / BN, maxtiles), NTH, SMEM_TOTAL>>>(
        xh, wgt, bias, nullptr, D_in, D_out);
    // GEMM2: out = y @ C^T  (y fp16 via cp.async; comp rounded in-loop)
    moe_hmma<false, false><<<dim3(S / BN, maxtiles), NTH, SMEM_TOTAL>>>(
        yh, comp, nullptr, out, D_out, S);
}